// round 1
// baseline (speedup 1.0000x reference)
#include <cuda_runtime.h>
#include <math.h>

#define NB 4
#define NC 1024
#define NT 2048
#define NH 16
#define CHD 64
#define NG 32
#define CPG 32
#define EPSV 1e-5f

// ---------------- scratch (allocation-free: device globals) ----------------
__device__ __align__(256) float g_xn[(long)NB * NC * NT];        // 32 MB
__device__ __align__(256) float g_qkv[(long)NB * 3 * NC * NT];   // 96 MB
__device__ __align__(256) float g_att[(long)NB * NC * NT];       // 32 MB

// ---------------- GroupNorm(32, C) fused (stats + normalize) ---------------
// One block per (b, g). The group's slab (32 channels x T) is contiguous.
__global__ void __launch_bounds__(256) gn_kernel(const float* __restrict__ x,
                                                 const float* __restrict__ gamma,
                                                 const float* __restrict__ beta) {
    int bg = blockIdx.x;
    int b = bg >> 5, g = bg & 31;
    long base = ((long)b * NC + (long)g * CPG) * NT;
    const float4* xp = (const float4*)(x + base);
    float4* op = (float4*)(g_xn + base);
    const int n4 = CPG * NT / 4;  // 16384
    float s = 0.f, s2 = 0.f;
    for (int i = threadIdx.x; i < n4; i += 256) {
        float4 v = xp[i];
        s += v.x + v.y + v.z + v.w;
        s2 += v.x * v.x + v.y * v.y + v.z * v.z + v.w * v.w;
    }
    __shared__ float red0[256], red1[256];
    red0[threadIdx.x] = s;
    red1[threadIdx.x] = s2;
    __syncthreads();
    for (int o = 128; o > 0; o >>= 1) {
        if (threadIdx.x < o) {
            red0[threadIdx.x] += red0[threadIdx.x + o];
            red1[threadIdx.x] += red1[threadIdx.x + o];
        }
        __syncthreads();
    }
    float inv_n = 1.f / (float)(CPG * NT);
    float mean = red0[0] * inv_n;
    float var = red1[0] * inv_n - mean * mean;
    float rstd = rsqrtf(var + EPSV);
    for (int i = threadIdx.x; i < n4; i += 256) {
        int c = g * CPG + (i >> 9);  // (i*4)/NT, NT=2048 -> i/512
        float ga = gamma[c] * rstd;
        float be = beta[c] - mean * ga;
        float4 v = xp[i];
        float4 o;
        o.x = v.x * ga + be;
        o.y = v.y * ga + be;
        o.z = v.z * ga + be;
        o.w = v.w * ga + be;
        op[i] = o;
    }
}

// ---------------- SGEMM 128x128x16, 256 threads, 8x8 microtile -------------
// C[m,n] = sum_k A[m,k]*B[k,n] + bias[m] (+ resid[m,n]); batched over z in B/C/resid.
__global__ void __launch_bounds__(256) sgemm_kernel(
    const float* __restrict__ A, const float* __restrict__ B,
    float* __restrict__ Cm, const float* __restrict__ bias,
    const float* __restrict__ resid,
    int M, int N, int K, long strB, long strC, long strR) {
    __shared__ float As[16][128];
    __shared__ float Bs[16][128];
    int tid = threadIdx.x;
    int bz = blockIdx.z;
    B += (long)bz * strB;
    Cm += (long)bz * strC;
    if (resid) resid += (long)bz * strR;
    int m0 = blockIdx.y * 128, n0 = blockIdx.x * 128;
    int ty = tid >> 4, tx = tid & 15;
    float acc[8][8];
#pragma unroll
    for (int i = 0; i < 8; i++)
#pragma unroll
        for (int j = 0; j < 8; j++) acc[i][j] = 0.f;

    for (int k0 = 0; k0 < K; k0 += 16) {
#pragma unroll
        for (int r = 0; r < 2; r++) {
            int id = tid + r * 256;
            int m = id >> 2, kv = id & 3;
            float4 va = *(const float4*)&A[(long)(m0 + m) * K + k0 + kv * 4];
            As[kv * 4 + 0][m] = va.x;
            As[kv * 4 + 1][m] = va.y;
            As[kv * 4 + 2][m] = va.z;
            As[kv * 4 + 3][m] = va.w;
            int row = id >> 5, c4 = id & 31;
            float4 vb = *(const float4*)&B[(long)(k0 + row) * N + n0 + c4 * 4];
            *(float4*)&Bs[row][c4 * 4] = vb;
        }
        __syncthreads();
#pragma unroll
        for (int k = 0; k < 16; k++) {
            float a[8], bb[8];
            *(float4*)&a[0] = *(const float4*)&As[k][ty * 8];
            *(float4*)&a[4] = *(const float4*)&As[k][ty * 8 + 4];
            *(float4*)&bb[0] = *(const float4*)&Bs[k][tx * 8];
            *(float4*)&bb[4] = *(const float4*)&Bs[k][tx * 8 + 4];
#pragma unroll
            for (int i = 0; i < 8; i++)
#pragma unroll
                for (int j = 0; j < 8; j++) acc[i][j] += a[i] * bb[j];
        }
        __syncthreads();
    }
#pragma unroll
    for (int i = 0; i < 8; i++) {
        int m = m0 + ty * 8 + i;
        float bi = bias[m];
#pragma unroll
        for (int j = 0; j < 8; j += 4) {
            long off = (long)m * N + n0 + tx * 8 + j;
            float4 r;
            r.x = acc[i][j] + bi;
            r.y = acc[i][j + 1] + bi;
            r.z = acc[i][j + 2] + bi;
            r.w = acc[i][j + 3] + bi;
            if (resid) {
                float4 rv = *(const float4*)&resid[off];
                r.x += rv.x;
                r.y += rv.y;
                r.z += rv.z;
                r.w += rv.w;
            }
            *(float4*)&Cm[off] = r;
        }
    }
}

// ---------------- Flash attention fp32 ------------------------------------
// grid(32, 64) = (q-tile of 64, b*H). block 256 threads = 16x16 grid, 4x4 frags.
#define VP 68
#define PP 68
__global__ void __launch_bounds__(256) attn_kernel() {
    extern __shared__ float sm[];
    float* Qs = sm;              // [64][64]
    float* Ks = Qs + 64 * 64;    // [64][64]
    float* Vs = Ks + 64 * 64;    // [64][VP]  Vs[s][c]
    float* Ps = Vs + 64 * VP;    // [64][PP]

    int tid = threadIdx.x;
    int ty = tid >> 4, tx = tid & 15;
    int t0 = blockIdx.x * 64;
    int bh = blockIdx.y;
    int b = bh >> 4, h = bh & 15;
    long qbase = ((long)b * 3 * NC + (long)h * CHD) * NT;
    const float* qp = g_qkv + qbase;
    const float* kp = g_qkv + qbase + (long)NC * NT;
    const float* vp = g_qkv + qbase + 2L * (long)NC * NT;

    for (int i = tid; i < 64 * 64; i += 256) {
        int c = i >> 6, q = i & 63;
        Qs[c * 64 + q] = qp[(long)c * NT + t0 + q];
    }

    float m_r[4], l_r[4], O[4][4];
#pragma unroll
    for (int i = 0; i < 4; i++) {
        m_r[i] = -1e30f;
        l_r[i] = 0.f;
#pragma unroll
        for (int j = 0; j < 4; j++) O[i][j] = 0.f;
    }
    __syncthreads();

    for (int s0 = 0; s0 < NT; s0 += 64) {
        for (int i = tid; i < 64 * 64; i += 256) {
            int c = i >> 6, s = i & 63;
            float kvv = kp[(long)c * NT + s0 + s];
            float vvv = vp[(long)c * NT + s0 + s];
            Ks[c * 64 + s] = kvv;
            Vs[s * VP + c] = vvv;
        }
        __syncthreads();

        float Sf[4][4];
#pragma unroll
        for (int i = 0; i < 4; i++)
#pragma unroll
            for (int j = 0; j < 4; j++) Sf[i][j] = 0.f;

#pragma unroll 8
        for (int c = 0; c < 64; c++) {
            float qa[4], ka[4];
            *(float4*)qa = *(const float4*)&Qs[c * 64 + ty * 4];
            *(float4*)ka = *(const float4*)&Ks[c * 64 + tx * 4];
#pragma unroll
            for (int i = 0; i < 4; i++)
#pragma unroll
                for (int j = 0; j < 4; j++) Sf[i][j] += qa[i] * ka[j];
        }

#pragma unroll
        for (int i = 0; i < 4; i++) {
#pragma unroll
            for (int j = 0; j < 4; j++) Sf[i][j] *= 0.125f;
            float mloc = fmaxf(fmaxf(Sf[i][0], Sf[i][1]), fmaxf(Sf[i][2], Sf[i][3]));
#pragma unroll
            for (int o = 8; o > 0; o >>= 1)
                mloc = fmaxf(mloc, __shfl_xor_sync(0xffffffffu, mloc, o));
            float mnew = fmaxf(m_r[i], mloc);
            float alpha = expf(m_r[i] - mnew);
            m_r[i] = mnew;
            float rs = 0.f;
#pragma unroll
            for (int j = 0; j < 4; j++) {
                float p = expf(Sf[i][j] - mnew);
                Sf[i][j] = p;
                rs += p;
            }
#pragma unroll
            for (int o = 8; o > 0; o >>= 1)
                rs += __shfl_xor_sync(0xffffffffu, rs, o);
            l_r[i] = l_r[i] * alpha + rs;
#pragma unroll
            for (int j = 0; j < 4; j++) O[i][j] *= alpha;
            float4 pw;
            pw.x = Sf[i][0];
            pw.y = Sf[i][1];
            pw.z = Sf[i][2];
            pw.w = Sf[i][3];
            *(float4*)&Ps[(ty * 4 + i) * PP + tx * 4] = pw;
        }
        __syncthreads();

#pragma unroll 4
        for (int s = 0; s < 64; s++) {
            float4 vv = *(const float4*)&Vs[s * VP + tx * 4];
            float p0 = Ps[(ty * 4 + 0) * PP + s];
            float p1 = Ps[(ty * 4 + 1) * PP + s];
            float p2 = Ps[(ty * 4 + 2) * PP + s];
            float p3 = Ps[(ty * 4 + 3) * PP + s];
            O[0][0] += p0 * vv.x; O[0][1] += p0 * vv.y; O[0][2] += p0 * vv.z; O[0][3] += p0 * vv.w;
            O[1][0] += p1 * vv.x; O[1][1] += p1 * vv.y; O[1][2] += p1 * vv.z; O[1][3] += p1 * vv.w;
            O[2][0] += p2 * vv.x; O[2][1] += p2 * vv.y; O[2][2] += p2 * vv.z; O[2][3] += p2 * vv.w;
            O[3][0] += p3 * vv.x; O[3][1] += p3 * vv.y; O[3][2] += p3 * vv.z; O[3][3] += p3 * vv.w;
        }
        __syncthreads();
    }

    float* ap = g_att + ((long)b * NC + (long)h * CHD) * NT;
#pragma unroll
    for (int i = 0; i < 4; i++) {
        float inv = 1.f / l_r[i];
        int q = t0 + ty * 4 + i;
#pragma unroll
        for (int j = 0; j < 4; j++) {
            int c = tx * 4 + j;
            ap[(long)c * NT + q] = O[i][j] * inv;
        }
    }
}

// ---------------- launch ----------------------------------------------------
extern "C" void kernel_launch(void* const* d_in, const int* in_sizes, int n_in,
                              void* d_out, int out_size) {
    const float* x = (const float*)d_in[0];
    const float* gn_scale = (const float*)d_in[1];
    const float* gn_bias = (const float*)d_in[2];
    const float* qkv_w = (const float*)d_in[3];
    const float* qkv_b = (const float*)d_in[4];
    const float* proj_w = (const float*)d_in[5];
    const float* proj_b = (const float*)d_in[6];
    float* out = (float*)d_out;

    float *xn_p, *qkv_p, *att_p;
    cudaGetSymbolAddress((void**)&xn_p, g_xn);
    cudaGetSymbolAddress((void**)&qkv_p, g_qkv);
    cudaGetSymbolAddress((void**)&att_p, g_att);

    const int attn_smem = (64 * 64 + 64 * 64 + 64 * VP + 64 * PP) * 4;
    cudaFuncSetAttribute(attn_kernel, cudaFuncAttributeMaxDynamicSharedMemorySize,
                         attn_smem);

    // 1) GroupNorm
    gn_kernel<<<NB * NG, 256>>>(x, gn_scale, gn_bias);

    // 2) QKV: [3C, C] @ xn[b] -> g_qkv
    dim3 g1(NT / 128, 3 * NC / 128, NB);
    sgemm_kernel<<<g1, 256>>>(qkv_w, xn_p, qkv_p, qkv_b, nullptr,
                              3 * NC, NT, NC,
                              (long)NC * NT, 3L * NC * NT, 0);

    // 3) Attention
    attn_kernel<<<dim3(NT / 64, NB * NH), 256, attn_smem>>>();

    // 4) proj + bias + residual -> d_out
    dim3 g2(NT / 128, NC / 128, NB);
    sgemm_kernel<<<g2, 256>>>(proj_w, att_p, out, proj_b, x,
                              NC, NT, NC,
                              (long)NC * NT, (long)NC * NT, (long)NC * NT);
}

// round 2
// speedup vs baseline: 2.1021x; 2.1021x over previous
#include <cuda_runtime.h>
#include <math.h>

#define NB 4
#define NC 1024
#define NT 2048
#define NH 16
#define CHD 64
#define NG 32
#define CPG 32
#define EPSV 1e-5f

// ---------------- scratch (allocation-free: device globals) ----------------
__device__ __align__(256) float g_xn[(long)NB * NC * NT];        // 32 MB
__device__ __align__(256) float g_qkv[(long)NB * 3 * NC * NT];   // 96 MB
__device__ __align__(256) float g_att[(long)NB * NC * NT];       // 32 MB

// ---------------- helpers ---------------------------------------------------
__device__ __forceinline__ float f2tf(float x) {
    unsigned r;
    asm("cvt.rna.tf32.f32 %0, %1;" : "=r"(r) : "f"(x));
    return __uint_as_float(r);
}

__device__ __forceinline__ void mma8(float* d, const float* a, float b0, float b1) {
    asm volatile(
        "mma.sync.aligned.m16n8k8.row.col.f32.tf32.tf32.f32 "
        "{%0,%1,%2,%3},{%4,%5,%6,%7},{%8,%9},{%0,%1,%2,%3};"
        : "+f"(d[0]), "+f"(d[1]), "+f"(d[2]), "+f"(d[3])
        : "r"(__float_as_uint(a[0])), "r"(__float_as_uint(a[1])),
          "r"(__float_as_uint(a[2])), "r"(__float_as_uint(a[3])),
          "r"(__float_as_uint(b0)), "r"(__float_as_uint(b1)));
}

// ---------------- GroupNorm(32, C) fused ------------------------------------
__global__ void __launch_bounds__(256) gn_kernel(const float* __restrict__ x,
                                                 const float* __restrict__ gamma,
                                                 const float* __restrict__ beta) {
    int bg = blockIdx.x;
    int b = bg >> 5, g = bg & 31;
    long base = ((long)b * NC + (long)g * CPG) * NT;
    const float4* xp = (const float4*)(x + base);
    float4* op = (float4*)(g_xn + base);
    const int n4 = CPG * NT / 4;
    float s = 0.f, s2 = 0.f;
    for (int i = threadIdx.x; i < n4; i += 256) {
        float4 v = xp[i];
        s += v.x + v.y + v.z + v.w;
        s2 += v.x * v.x + v.y * v.y + v.z * v.z + v.w * v.w;
    }
    __shared__ float red0[256], red1[256];
    red0[threadIdx.x] = s;
    red1[threadIdx.x] = s2;
    __syncthreads();
    for (int o = 128; o > 0; o >>= 1) {
        if (threadIdx.x < o) {
            red0[threadIdx.x] += red0[threadIdx.x + o];
            red1[threadIdx.x] += red1[threadIdx.x + o];
        }
        __syncthreads();
    }
    float inv_n = 1.f / (float)(CPG * NT);
    float mean = red0[0] * inv_n;
    float var = red1[0] * inv_n - mean * mean;
    float rstd = rsqrtf(var + EPSV);
    for (int i = threadIdx.x; i < n4; i += 256) {
        int c = g * CPG + (i >> 9);
        float ga = gamma[c] * rstd;
        float be = beta[c] - mean * ga;
        float4 v = xp[i];
        float4 o;
        o.x = v.x * ga + be;
        o.y = v.y * ga + be;
        o.z = v.z * ga + be;
        o.w = v.w * ga + be;
        op[i] = o;
    }
}

// ---------------- TF32 tensor-core GEMM 128x128 ------------------------------
// C[m,n] = sum_k A[m,k]*B[k,n] + bias[m] (+ resid); batched over z.
#define GPAD 136
__global__ void __launch_bounds__(256) sgemm_tf32(
    const float* __restrict__ A, const float* __restrict__ B,
    float* __restrict__ Cm, const float* __restrict__ bias,
    const float* __restrict__ resid,
    int M, int N, int K, long strB, long strC, long strR) {
    __shared__ float As[16][GPAD];
    __shared__ float Bs[16][GPAD];
    int tid = threadIdx.x;
    int bz = blockIdx.z;
    B += (long)bz * strB;
    Cm += (long)bz * strC;
    if (resid) resid += (long)bz * strR;
    int m0 = blockIdx.y * 128, n0 = blockIdx.x * 128;
    int wid = tid >> 5, lane = tid & 31;
    int gid = lane >> 2, tq = lane & 3;
    int wm = (wid >> 1) * 32, wn = (wid & 1) * 64;
    float acc[2][8][4] = {};

    for (int k0 = 0; k0 < K; k0 += 16) {
#pragma unroll
        for (int r = 0; r < 2; r++) {
            int id = tid + r * 256;
            int m = id >> 2, kv = (id & 3) * 4;
            float4 va = *(const float4*)&A[(long)(m0 + m) * K + k0 + kv];
            As[kv + 0][m] = f2tf(va.x);
            As[kv + 1][m] = f2tf(va.y);
            As[kv + 2][m] = f2tf(va.z);
            As[kv + 3][m] = f2tf(va.w);
            int row = id >> 5, c4 = (id & 31) * 4;
            float4 vb = *(const float4*)&B[(long)(k0 + row) * N + n0 + c4];
            Bs[row][c4 + 0] = f2tf(vb.x);
            Bs[row][c4 + 1] = f2tf(vb.y);
            Bs[row][c4 + 2] = f2tf(vb.z);
            Bs[row][c4 + 3] = f2tf(vb.w);
        }
        __syncthreads();
#pragma unroll
        for (int kk = 0; kk < 16; kk += 8) {
            float a[2][4];
#pragma unroll
            for (int mi = 0; mi < 2; mi++) {
                int m = wm + mi * 16 + gid;
                a[mi][0] = As[kk + tq][m];
                a[mi][1] = As[kk + tq][m + 8];
                a[mi][2] = As[kk + tq + 4][m];
                a[mi][3] = As[kk + tq + 4][m + 8];
            }
            float b[8][2];
#pragma unroll
            for (int nj = 0; nj < 8; nj++) {
                int n = wn + nj * 8 + gid;
                b[nj][0] = Bs[kk + tq][n];
                b[nj][1] = Bs[kk + tq + 4][n];
            }
#pragma unroll
            for (int mi = 0; mi < 2; mi++)
#pragma unroll
                for (int nj = 0; nj < 8; nj++)
                    mma8(acc[mi][nj], a[mi], b[nj][0], b[nj][1]);
        }
        __syncthreads();
    }
#pragma unroll
    for (int mi = 0; mi < 2; mi++) {
#pragma unroll
        for (int rr = 0; rr < 2; rr++) {
            int m = m0 + wm + mi * 16 + gid + rr * 8;
            float bi = bias[m];
#pragma unroll
            for (int nj = 0; nj < 8; nj++) {
                int n = n0 + wn + nj * 8 + tq * 2;
                long off = (long)m * N + n;
                float2 r;
                r.x = acc[mi][nj][rr * 2 + 0] + bi;
                r.y = acc[mi][nj][rr * 2 + 1] + bi;
                if (resid) {
                    float2 rv = *(const float2*)&resid[off];
                    r.x += rv.x;
                    r.y += rv.y;
                }
                *(float2*)&Cm[off] = r;
            }
        }
    }
}

// ---------------- Flash attention, TF32 tensor cores -------------------------
// grid(16, 64): 128-query tile per block, 8 warps x 16 q-rows each.
#define KPAD 72
__global__ void __launch_bounds__(256) attn_tf32() {
    extern __shared__ float sm[];
    float* Ks = sm;               // [64][KPAD]
    float* Vs = sm + 64 * KPAD;   // [64][KPAD]

    int tid = threadIdx.x, wid = tid >> 5, lane = tid & 31;
    int gid = lane >> 2, tq = lane & 3;
    int t0 = blockIdx.x * 128;
    int bh = blockIdx.y;
    int b = bh >> 4, h = bh & 15;
    long qb = ((long)b * 3 * NC + (long)h * CHD) * NT;
    const float* qp = g_qkv + qb;
    const float* kp = qp + (long)NC * NT;
    const float* vp = qp + 2L * (long)NC * NT;
    int wq = wid * 16;

    // stage Q[c][q] (pad 136) into smem, then register A-fragments
    for (int i = tid; i < 64 * 32; i += 256) {
        int c = i >> 5, q4 = (i & 31) * 4;
        float4 v = *(const float4*)&qp[(long)c * NT + t0 + q4];
        float* d = sm + c * 136 + q4;
        d[0] = f2tf(v.x);
        d[1] = f2tf(v.y);
        d[2] = f2tf(v.z);
        d[3] = f2tf(v.w);
    }
    __syncthreads();
    float qf[8][4];
#pragma unroll
    for (int kk = 0; kk < 8; kk++) {
        const float* b0 = sm + (kk * 8 + tq) * 136;
        const float* b1 = sm + (kk * 8 + tq + 4) * 136;
        qf[kk][0] = b0[wq + gid];
        qf[kk][1] = b0[wq + gid + 8];
        qf[kk][2] = b1[wq + gid];
        qf[kk][3] = b1[wq + gid + 8];
    }
    __syncthreads();

    float m_[2] = {-1e30f, -1e30f}, l_[2] = {0.f, 0.f};
    float O[8][4] = {};

    for (int s0 = 0; s0 < NT; s0 += 64) {
        for (int i = tid; i < 64 * 16; i += 256) {
            int c = i >> 4, s4 = (i & 15) * 4;
            float4 kv4 = *(const float4*)&kp[(long)c * NT + s0 + s4];
            float* kd = Ks + c * KPAD + s4;
            kd[0] = f2tf(kv4.x);
            kd[1] = f2tf(kv4.y);
            kd[2] = f2tf(kv4.z);
            kd[3] = f2tf(kv4.w);
            float4 vv4 = *(const float4*)&vp[(long)c * NT + s0 + s4];
            float* vd = Vs + c * KPAD + s4;
            vd[0] = f2tf(vv4.x);
            vd[1] = f2tf(vv4.y);
            vd[2] = f2tf(vv4.z);
            vd[3] = f2tf(vv4.w);
        }
        __syncthreads();

        // S = Q^T K  (m=16 q, n=64 s, k=64 c)
        float S[8][4] = {};
#pragma unroll
        for (int kk = 0; kk < 8; kk++) {
            float bq[8][2];
#pragma unroll
            for (int nj = 0; nj < 8; nj++) {
                bq[nj][0] = Ks[(kk * 8 + tq) * KPAD + nj * 8 + gid];
                bq[nj][1] = Ks[(kk * 8 + tq + 4) * KPAD + nj * 8 + gid];
            }
#pragma unroll
            for (int nj = 0; nj < 8; nj++)
                mma8(S[nj], qf[kk], bq[nj][0], bq[nj][1]);
        }

        // fragment-level online softmax (2 rows per thread: gid, gid+8)
#pragma unroll
        for (int nj = 0; nj < 8; nj++)
#pragma unroll
            for (int j = 0; j < 4; j++) S[nj][j] *= 0.125f;
#pragma unroll
        for (int rr = 0; rr < 2; rr++) {
            float mx = -1e30f;
#pragma unroll
            for (int nj = 0; nj < 8; nj++)
                mx = fmaxf(mx, fmaxf(S[nj][rr * 2], S[nj][rr * 2 + 1]));
            mx = fmaxf(mx, __shfl_xor_sync(0xffffffffu, mx, 1));
            mx = fmaxf(mx, __shfl_xor_sync(0xffffffffu, mx, 2));
            float mnew = fmaxf(m_[rr], mx);
            float alpha = __expf(m_[rr] - mnew);
            m_[rr] = mnew;
            float rs = 0.f;
#pragma unroll
            for (int nj = 0; nj < 8; nj++) {
                float p0 = __expf(S[nj][rr * 2] - mnew);
                float p1 = __expf(S[nj][rr * 2 + 1] - mnew);
                S[nj][rr * 2] = p0;
                S[nj][rr * 2 + 1] = p1;
                rs += p0 + p1;
            }
            rs += __shfl_xor_sync(0xffffffffu, rs, 1);
            rs += __shfl_xor_sync(0xffffffffu, rs, 2);
            l_[rr] = l_[rr] * alpha + rs;
#pragma unroll
            for (int nj = 0; nj < 8; nj++) {
                O[nj][rr * 2] *= alpha;
                O[nj][rr * 2 + 1] *= alpha;
            }
        }

        // P -> tf32 A-fragments (C-frag reg permutation, k-order permuted)
#pragma unroll
        for (int kk = 0; kk < 8; kk++)
#pragma unroll
            for (int j = 0; j < 4; j++) S[kk][j] = f2tf(S[kk][j]);

        // O += P V^T  (m=16 q, n=64 c, k=64 s; phys k p<4 -> s=2p, p>=4 -> s=2(p-4)+1)
#pragma unroll
        for (int nj = 0; nj < 8; nj++) {
            const float* vrow = Vs + (nj * 8 + gid) * KPAD;
#pragma unroll
            for (int kk = 0; kk < 8; kk++) {
                float b0 = vrow[kk * 8 + 2 * tq];
                float b1 = vrow[kk * 8 + 2 * tq + 1];
                float a[4] = {S[kk][0], S[kk][2], S[kk][1], S[kk][3]};
                mma8(O[nj], a, b0, b1);
            }
        }
        __syncthreads();
    }

    float inv0 = 1.f / l_[0], inv1 = 1.f / l_[1];
    float* ap = g_att + ((long)b * NC + (long)h * CHD) * NT;
    int q = t0 + wq + gid;
#pragma unroll
    for (int nj = 0; nj < 8; nj++) {
        int c = nj * 8 + 2 * tq;
        ap[(long)c * NT + q] = O[nj][0] * inv0;
        ap[(long)(c + 1) * NT + q] = O[nj][1] * inv0;
        ap[(long)c * NT + q + 8] = O[nj][2] * inv1;
        ap[(long)(c + 1) * NT + q + 8] = O[nj][3] * inv1;
    }
}

// ---------------- launch ------------------------------------------------------
extern "C" void kernel_launch(void* const* d_in, const int* in_sizes, int n_in,
                              void* d_out, int out_size) {
    const float* x = (const float*)d_in[0];
    const float* gn_scale = (const float*)d_in[1];
    const float* gn_bias = (const float*)d_in[2];
    const float* qkv_w = (const float*)d_in[3];
    const float* qkv_b = (const float*)d_in[4];
    const float* proj_w = (const float*)d_in[5];
    const float* proj_b = (const float*)d_in[6];
    float* out = (float*)d_out;

    float *xn_p, *qkv_p, *att_p;
    cudaGetSymbolAddress((void**)&xn_p, g_xn);
    cudaGetSymbolAddress((void**)&qkv_p, g_qkv);
    cudaGetSymbolAddress((void**)&att_p, g_att);

    const int attn_smem = 2 * 64 * KPAD * 4;  // 36864 B (Q staging overlays)
    cudaFuncSetAttribute(attn_tf32, cudaFuncAttributeMaxDynamicSharedMemorySize,
                         attn_smem);

    // 1) GroupNorm
    gn_kernel<<<NB * NG, 256>>>(x, gn_scale, gn_bias);

    // 2) QKV GEMM: [3C, C] @ xn[b] -> g_qkv
    dim3 g1(NT / 128, 3 * NC / 128, NB);
    sgemm_tf32<<<g1, 256>>>(qkv_w, xn_p, qkv_p, qkv_b, nullptr,
                            3 * NC, NT, NC,
                            (long)NC * NT, 3L * NC * NT, 0);

    // 3) Attention
    attn_tf32<<<dim3(NT / 128, NB * NH), 256, attn_smem>>>();

    // 4) proj + bias + residual -> d_out
    dim3 g2(NT / 128, NC / 128, NB);
    sgemm_tf32<<<g2, 256>>>(proj_w, att_p, out, proj_b, x,
                            NC, NT, NC,
                            (long)NC * NT, (long)NC * NT, (long)NC * NT);
}

// round 3
// speedup vs baseline: 4.6741x; 2.2235x over previous
#include <cuda_runtime.h>
#include <cuda_bf16.h>
#include <math.h>

#define NB 4
#define NC 1024
#define NT 2048
#define NH 16
#define CPG 32
#define EPSV 1e-5f

using bf16 = __nv_bfloat16;
using bf162 = __nv_bfloat162;

// ---------------- scratch (allocation-free: device globals) ----------------
__device__ __align__(256) bf16 g_xn[(long)NB * NC * NT];        // 16 MB
__device__ __align__(256) bf16 g_qkv[(long)NB * 3 * NC * NT];   // 48 MB
__device__ __align__(256) bf16 g_att[(long)NB * NC * NT];       // 16 MB

__device__ __forceinline__ unsigned pk(float a, float b) {
    bf162 t = __floats2bfloat162_rn(a, b);
    return *(unsigned*)&t;
}

__device__ __forceinline__ void mma16(float* d, const unsigned* a, unsigned b0,
                                      unsigned b1) {
    asm volatile(
        "mma.sync.aligned.m16n8k16.row.col.f32.bf16.bf16.f32 "
        "{%0,%1,%2,%3},{%4,%5,%6,%7},{%8,%9},{%0,%1,%2,%3};"
        : "+f"(d[0]), "+f"(d[1]), "+f"(d[2]), "+f"(d[3])
        : "r"(a[0]), "r"(a[1]), "r"(a[2]), "r"(a[3]), "r"(b0), "r"(b1));
}

// ---------------- GroupNorm(32, C), bf16 output ------------------------------
__global__ void __launch_bounds__(256) gn_kernel(const float* __restrict__ x,
                                                 const float* __restrict__ gamma,
                                                 const float* __restrict__ beta) {
    int bg = blockIdx.x;
    int b = bg >> 5, g = bg & 31;
    long base = ((long)b * NC + (long)g * CPG) * NT;
    const float4* xp = (const float4*)(x + base);
    uint2* op = (uint2*)(g_xn + base);
    const int n4 = CPG * NT / 4;
    float s = 0.f, s2 = 0.f;
    for (int i = threadIdx.x; i < n4; i += 256) {
        float4 v = xp[i];
        s += v.x + v.y + v.z + v.w;
        s2 += v.x * v.x + v.y * v.y + v.z * v.z + v.w * v.w;
    }
    __shared__ float red0[256], red1[256];
    red0[threadIdx.x] = s;
    red1[threadIdx.x] = s2;
    __syncthreads();
    for (int o = 128; o > 0; o >>= 1) {
        if (threadIdx.x < o) {
            red0[threadIdx.x] += red0[threadIdx.x + o];
            red1[threadIdx.x] += red1[threadIdx.x + o];
        }
        __syncthreads();
    }
    float inv_n = 1.f / (float)(CPG * NT);
    float mean = red0[0] * inv_n;
    float var = red1[0] * inv_n - mean * mean;
    float rstd = rsqrtf(var + EPSV);
    for (int i = threadIdx.x; i < n4; i += 256) {
        int c = g * CPG + (i >> 9);
        float ga = gamma[c] * rstd;
        float be = beta[c] - mean * ga;
        float4 v = xp[i];
        uint2 o;
        o.x = pk(v.x * ga + be, v.y * ga + be);
        o.y = pk(v.z * ga + be, v.w * ga + be);
        op[i] = o;
    }
}

// ---------------- bf16 tensor-core GEMM 128x128, BK=32, reg prefetch --------
#define BK 32
#define APAD 40
#define BPAD 40

template <bool BF16OUT>
__global__ void __launch_bounds__(256) gemm_bf16(
    const float* __restrict__ A, const bf16* __restrict__ B,
    void* __restrict__ Cv, const float* __restrict__ bias,
    const float* __restrict__ resid, int N, int K,
    long strB, long strC, long strR) {
    __shared__ bf16 As[128 * APAD];
    __shared__ bf16 Bs[128 * BPAD];
    int tid = threadIdx.x, bz = blockIdx.z;
    B += (long)bz * strB;
    const int m0 = blockIdx.y * 128, n0 = blockIdx.x * 128;
    int wid = tid >> 5, lane = tid & 31, gid = lane >> 2, tq = lane & 3;
    int wm = (wid >> 1) * 32, wn = (wid & 1) * 64;
    float acc[2][8][4] = {};

    float4 av[4];
    uint4 bv[2];

#define LOADG(k0)                                                            \
    {                                                                        \
        _Pragma("unroll") for (int r = 0; r < 4; r++) {                      \
            int i = tid + r * 256;                                           \
            av[r] = *(const float4*)&A[(long)(m0 + (i >> 3)) * K + (k0) +    \
                                       (i & 7) * 4];                         \
        }                                                                    \
        _Pragma("unroll") for (int r = 0; r < 2; r++) {                      \
            int i = tid + r * 256;                                           \
            bv[r] = *(const uint4*)&B[(long)((k0) + (i >> 4)) * N + n0 +     \
                                      (i & 15) * 8];                         \
        }                                                                    \
    }
#define STORES()                                                             \
    {                                                                        \
        _Pragma("unroll") for (int r = 0; r < 4; r++) {                      \
            int i = tid + r * 256;                                           \
            int m = i >> 3, k4 = (i & 7) * 4;                                \
            *(bf162*)&As[m * APAD + k4] =                                    \
                __floats2bfloat162_rn(av[r].x, av[r].y);                     \
            *(bf162*)&As[m * APAD + k4 + 2] =                                \
                __floats2bfloat162_rn(av[r].z, av[r].w);                     \
        }                                                                    \
        _Pragma("unroll") for (int r = 0; r < 2; r++) {                      \
            int i = tid + r * 256;                                           \
            int k = i >> 4, bb = (i & 15);                                   \
            const bf16* s = (const bf16*)&bv[r];                             \
            _Pragma("unroll") for (int jj = 0; jj < 8; jj++) {               \
                int j = (jj + bb) & 7;                                       \
                Bs[(bb * 8 + j) * BPAD + k] = s[j];                          \
            }                                                                \
        }                                                                    \
    }

    LOADG(0);
    STORES();
    __syncthreads();
    const int nkt = K / BK;
    for (int kt = 0; kt < nkt; kt++) {
        if (kt + 1 < nkt) LOADG((kt + 1) * BK);
#pragma unroll
        for (int kk = 0; kk < 2; kk++) {
            unsigned a[2][4];
#pragma unroll
            for (int mi = 0; mi < 2; mi++) {
                const bf16* p = &As[(wm + mi * 16 + gid) * APAD + kk * 16 + 2 * tq];
                a[mi][0] = *(const unsigned*)p;
                a[mi][1] = *(const unsigned*)(p + 8 * APAD);
                a[mi][2] = *(const unsigned*)(p + 8);
                a[mi][3] = *(const unsigned*)(p + 8 * APAD + 8);
            }
#pragma unroll
            for (int nj = 0; nj < 8; nj++) {
                const bf16* p = &Bs[(wn + nj * 8 + gid) * BPAD + kk * 16 + 2 * tq];
                unsigned b0 = *(const unsigned*)p;
                unsigned b1 = *(const unsigned*)(p + 8);
#pragma unroll
                for (int mi = 0; mi < 2; mi++) mma16(acc[mi][nj], a[mi], b0, b1);
            }
        }
        __syncthreads();
        if (kt + 1 < nkt) {
            STORES();
        }
        __syncthreads();
    }

#pragma unroll
    for (int mi = 0; mi < 2; mi++) {
#pragma unroll
        for (int rr = 0; rr < 2; rr++) {
            int m = m0 + wm + mi * 16 + gid + rr * 8;
            float bi = bias[m];
            if (BF16OUT) {
                bf16* Cm = (bf16*)Cv + (long)bz * strC;
#pragma unroll
                for (int nj = 0; nj < 8; nj++) {
                    int n = n0 + wn + nj * 8 + tq * 2;
                    *(bf162*)&Cm[(long)m * N + n] = __floats2bfloat162_rn(
                        acc[mi][nj][rr * 2] + bi, acc[mi][nj][rr * 2 + 1] + bi);
                }
            } else {
                float* Cm = (float*)Cv + (long)bz * strC;
                const float* rp = resid + (long)bz * strR;
#pragma unroll
                for (int nj = 0; nj < 8; nj++) {
                    int n = n0 + wn + nj * 8 + tq * 2;
                    long off = (long)m * N + n;
                    float2 rv = *(const float2*)&rp[off];
                    float2 r;
                    r.x = acc[mi][nj][rr * 2] + bi + rv.x;
                    r.y = acc[mi][nj][rr * 2 + 1] + bi + rv.y;
                    *(float2*)&Cm[off] = r;
                }
            }
        }
    }
}

// ---------------- Flash attention, bf16 m16n8k16 -----------------------------
#define QP 72
#define KP 72
__global__ void __launch_bounds__(256) attn_bf16() {
    __shared__ bf16 Qs[128 * QP];
    __shared__ bf16 Ks[64 * KP];
    __shared__ bf16 Vs[64 * KP];

    int tid = threadIdx.x, wid = tid >> 5, lane = tid & 31;
    int gid = lane >> 2, tq = lane & 3;
    int t0 = blockIdx.x * 128;
    int bh = blockIdx.y, b = bh >> 4, h = bh & 15;
    const bf16* qp = g_qkv + ((long)b * 3 * NC + (long)h * 64) * NT;
    const bf16* kp = qp + (long)NC * NT;
    const bf16* vp = qp + 2L * (long)NC * NT;
    int wq = wid * 16;

    // stage Q transposed: Qs[q][c]
#pragma unroll
    for (int r = 0; r < 4; r++) {
        int i = tid + r * 256;
        int c = i >> 4, a2 = i & 15;
        uint4 v = *(const uint4*)&qp[(long)c * NT + t0 + a2 * 8];
        const bf16* s = (const bf16*)&v;
#pragma unroll
        for (int jj = 0; jj < 8; jj++) {
            int j = (jj + a2) & 7;
            Qs[(a2 * 8 + j) * QP + c] = s[j];
        }
    }
    __syncthreads();
    unsigned qf[4][4];
#pragma unroll
    for (int kk = 0; kk < 4; kk++) {
        const bf16* p = &Qs[(wq + gid) * QP + kk * 16 + 2 * tq];
        qf[kk][0] = *(const unsigned*)p;
        qf[kk][1] = *(const unsigned*)(p + 8 * QP);
        qf[kk][2] = *(const unsigned*)(p + 8);
        qf[kk][3] = *(const unsigned*)(p + 8 * QP + 8);
    }

    float m_[2] = {-1e30f, -1e30f}, l_[2] = {0.f, 0.f};
    float O[8][4] = {};

    uint4 kvv[2], vvv[2];
#define LOADKV(s0)                                                           \
    {                                                                        \
        _Pragma("unroll") for (int r = 0; r < 2; r++) {                      \
            int i = tid + r * 256;                                           \
            int c = i >> 3, a = i & 7;                                       \
            kvv[r] = *(const uint4*)&kp[(long)c * NT + (s0) + a * 8];        \
            vvv[r] = *(const uint4*)&vp[(long)c * NT + (s0) + a * 8];        \
        }                                                                    \
    }
#define STOREKV()                                                            \
    {                                                                        \
        _Pragma("unroll") for (int r = 0; r < 2; r++) {                      \
            int i = tid + r * 256;                                           \
            int c = i >> 3, a = i & 7;                                       \
            const bf16* s = (const bf16*)&kvv[r];                            \
            _Pragma("unroll") for (int jj = 0; jj < 8; jj++) {               \
                int j = (jj + a) & 7;                                        \
                Ks[(a * 8 + j) * KP + c] = s[j];                             \
            }                                                                \
            *(uint4*)&Vs[c * KP + a * 8] = vvv[r];                           \
        }                                                                    \
    }

    LOADKV(0);
    STOREKV();
    __syncthreads();

    for (int s0 = 0; s0 < NT; s0 += 64) {
        if (s0 + 64 < NT) LOADKV(s0 + 64);

        // S = Q K^T  (m=16 q, n=64 s, k=64 c)
        float S[8][4] = {};
#pragma unroll
        for (int kk = 0; kk < 4; kk++) {
#pragma unroll
            for (int nj = 0; nj < 8; nj++) {
                const bf16* p = &Ks[(nj * 8 + gid) * KP + kk * 16 + 2 * tq];
                mma16(S[nj], qf[kk], *(const unsigned*)p, *(const unsigned*)(p + 8));
            }
        }

        // fragment online softmax (rows gid / gid+8)
#pragma unroll
        for (int nj = 0; nj < 8; nj++)
#pragma unroll
            for (int j = 0; j < 4; j++) S[nj][j] *= 0.125f;
#pragma unroll
        for (int rr = 0; rr < 2; rr++) {
            float mx = -1e30f;
#pragma unroll
            for (int nj = 0; nj < 8; nj++)
                mx = fmaxf(mx, fmaxf(S[nj][rr * 2], S[nj][rr * 2 + 1]));
            mx = fmaxf(mx, __shfl_xor_sync(0xffffffffu, mx, 1));
            mx = fmaxf(mx, __shfl_xor_sync(0xffffffffu, mx, 2));
            float mnew = fmaxf(m_[rr], mx);
            float alpha = __expf(m_[rr] - mnew);
            m_[rr] = mnew;
            float rs = 0.f;
#pragma unroll
            for (int nj = 0; nj < 8; nj++) {
                float p0 = __expf(S[nj][rr * 2] - mnew);
                float p1 = __expf(S[nj][rr * 2 + 1] - mnew);
                S[nj][rr * 2] = p0;
                S[nj][rr * 2 + 1] = p1;
                rs += p0 + p1;
            }
            rs += __shfl_xor_sync(0xffffffffu, rs, 1);
            rs += __shfl_xor_sync(0xffffffffu, rs, 2);
            l_[rr] = l_[rr] * alpha + rs;
#pragma unroll
            for (int nj = 0; nj < 8; nj++) {
                O[nj][rr * 2] *= alpha;
                O[nj][rr * 2 + 1] *= alpha;
            }
        }

        // pack P to bf16 A-fragments (C-layout maps 1:1 onto A-layout)
        unsigned pa[4][4];
#pragma unroll
        for (int kk = 0; kk < 4; kk++) {
            pa[kk][0] = pk(S[2 * kk][0], S[2 * kk][1]);
            pa[kk][1] = pk(S[2 * kk][2], S[2 * kk][3]);
            pa[kk][2] = pk(S[2 * kk + 1][0], S[2 * kk + 1][1]);
            pa[kk][3] = pk(S[2 * kk + 1][2], S[2 * kk + 1][3]);
        }

        // O += P V^T  (m=16 q, n=64 c, k=64 s)
#pragma unroll
        for (int nj = 0; nj < 8; nj++) {
#pragma unroll
            for (int kk = 0; kk < 4; kk++) {
                const bf16* p = &Vs[(nj * 8 + gid) * KP + kk * 16 + 2 * tq];
                mma16(O[nj], pa[kk], *(const unsigned*)p, *(const unsigned*)(p + 8));
            }
        }
        __syncthreads();
        if (s0 + 64 < NT) {
            STOREKV();
        }
        __syncthreads();
    }

    float inv0 = 1.f / l_[0], inv1 = 1.f / l_[1];
    bf16* ap = g_att + ((long)b * NC + (long)h * 64) * NT;
    int q = t0 + wq + gid;
#pragma unroll
    for (int nj = 0; nj < 8; nj++) {
        int c = nj * 8 + 2 * tq;
        ap[(long)c * NT + q] = __float2bfloat16(O[nj][0] * inv0);
        ap[(long)(c + 1) * NT + q] = __float2bfloat16(O[nj][1] * inv0);
        ap[(long)c * NT + q + 8] = __float2bfloat16(O[nj][2] * inv1);
        ap[(long)(c + 1) * NT + q + 8] = __float2bfloat16(O[nj][3] * inv1);
    }
}

// ---------------- launch ------------------------------------------------------
extern "C" void kernel_launch(void* const* d_in, const int* in_sizes, int n_in,
                              void* d_out, int out_size) {
    const float* x = (const float*)d_in[0];
    const float* gn_scale = (const float*)d_in[1];
    const float* gn_bias = (const float*)d_in[2];
    const float* qkv_w = (const float*)d_in[3];
    const float* qkv_b = (const float*)d_in[4];
    const float* proj_w = (const float*)d_in[5];
    const float* proj_b = (const float*)d_in[6];
    float* out = (float*)d_out;

    bf16 *xn_p, *qkv_p, *att_p;
    cudaGetSymbolAddress((void**)&xn_p, g_xn);
    cudaGetSymbolAddress((void**)&qkv_p, g_qkv);
    cudaGetSymbolAddress((void**)&att_p, g_att);

    // 1) GroupNorm -> bf16 xn
    gn_kernel<<<NB * 32, 256>>>(x, gn_scale, gn_bias);

    // 2) QKV GEMM: qkv_w[3C,C] @ xn[b] -> g_qkv (bf16)
    dim3 g1(NT / 128, 3 * NC / 128, NB);
    gemm_bf16<true><<<g1, 256>>>(qkv_w, xn_p, qkv_p, qkv_b, nullptr,
                                 NT, NC, (long)NC * NT, 3L * NC * NT, 0);

    // 3) Attention -> g_att (bf16)
    attn_bf16<<<dim3(NT / 128, NB * NH), 256>>>();

    // 4) proj + bias + residual -> d_out (fp32)
    dim3 g2(NT / 128, NC / 128, NB);
    gemm_bf16<false><<<g2, 256>>>(proj_w, att_p, out, proj_b, x,
                                  NT, NC, (long)NC * NT, (long)NC * NT,
                                  (long)NC * NT);
}

// round 4
// speedup vs baseline: 4.6777x; 1.0008x over previous
#include <cuda_runtime.h>
#include <cuda_bf16.h>
#include <math.h>

#define NB 4
#define NC 1024
#define NT 2048
#define NH 16
#define CPG 32
#define EPSV 1e-5f

using bf16 = __nv_bfloat16;
using bf162 = __nv_bfloat162;

// ---------------- scratch (allocation-free: device globals) ----------------
__device__ __align__(256) bf16 g_xn[(long)NB * NC * NT];        // 16 MB
__device__ __align__(256) bf16 g_qkv[(long)NB * 3 * NC * NT];   // 48 MB
__device__ __align__(256) bf16 g_att[(long)NB * NC * NT];       // 16 MB

__device__ __forceinline__ unsigned pk(float a, float b) {
    bf162 t = __floats2bfloat162_rn(a, b);
    return *(unsigned*)&t;
}

__device__ __forceinline__ void mma16(float* d, const unsigned* a, unsigned b0,
                                      unsigned b1) {
    asm volatile(
        "mma.sync.aligned.m16n8k16.row.col.f32.bf16.bf16.f32 "
        "{%0,%1,%2,%3},{%4,%5,%6,%7},{%8,%9},{%0,%1,%2,%3};"
        : "+f"(d[0]), "+f"(d[1]), "+f"(d[2]), "+f"(d[3])
        : "r"(a[0]), "r"(a[1]), "r"(a[2]), "r"(a[3]), "r"(b0), "r"(b1));
}

// ---------------- GroupNorm(32, C), bf16 output ------------------------------
__global__ void __launch_bounds__(256) gn_kernel(const float* __restrict__ x,
                                                 const float* __restrict__ gamma,
                                                 const float* __restrict__ beta) {
    int bg = blockIdx.x;
    int b = bg >> 5, g = bg & 31;
    long base = ((long)b * NC + (long)g * CPG) * NT;
    const float4* xp = (const float4*)(x + base);
    uint2* op = (uint2*)(g_xn + base);
    const int n4 = CPG * NT / 4;
    float s = 0.f, s2 = 0.f;
    for (int i = threadIdx.x; i < n4; i += 256) {
        float4 v = xp[i];
        s += v.x + v.y + v.z + v.w;
        s2 += v.x * v.x + v.y * v.y + v.z * v.z + v.w * v.w;
    }
    __shared__ float red0[256], red1[256];
    red0[threadIdx.x] = s;
    red1[threadIdx.x] = s2;
    __syncthreads();
    for (int o = 128; o > 0; o >>= 1) {
        if (threadIdx.x < o) {
            red0[threadIdx.x] += red0[threadIdx.x + o];
            red1[threadIdx.x] += red1[threadIdx.x + o];
        }
        __syncthreads();
    }
    float inv_n = 1.f / (float)(CPG * NT);
    float mean = red0[0] * inv_n;
    float var = red1[0] * inv_n - mean * mean;
    float rstd = rsqrtf(var + EPSV);
    for (int i = threadIdx.x; i < n4; i += 256) {
        int c = g * CPG + (i >> 9);
        float ga = gamma[c] * rstd;
        float be = beta[c] - mean * ga;
        float4 v = xp[i];
        uint2 o;
        o.x = pk(v.x * ga + be, v.y * ga + be);
        o.y = pk(v.z * ga + be, v.w * ga + be);
        op[i] = o;
    }
}

// ---------------- bf16 tensor-core GEMM 128x128, BK=32, reg prefetch --------
#define BK 32
#define APAD 40
#define BPAD 40

template <bool BF16OUT>
__global__ void __launch_bounds__(256) gemm_bf16(
    const float* __restrict__ A, const bf16* __restrict__ B,
    void* __restrict__ Cv, const float* __restrict__ bias,
    const float* __restrict__ resid, int N, int K,
    long strB, long strC, long strR) {
    __shared__ bf16 As[128 * APAD];
    __shared__ bf16 Bs[128 * BPAD];
    int tid = threadIdx.x, bz = blockIdx.z;
    B += (long)bz * strB;
    const int m0 = blockIdx.y * 128, n0 = blockIdx.x * 128;
    int wid = tid >> 5, lane = tid & 31, gid = lane >> 2, tq = lane & 3;
    int wm = (wid >> 1) * 32, wn = (wid & 1) * 64;
    float acc[2][8][4] = {};

    float4 av[4];
    uint4 bv[2];

#define LOADG(k0)                                                            \
    {                                                                        \
        _Pragma("unroll") for (int r = 0; r < 4; r++) {                      \
            int i = tid + r * 256;                                           \
            av[r] = *(const float4*)&A[(long)(m0 + (i >> 3)) * K + (k0) +    \
                                       (i & 7) * 4];                         \
        }                                                                    \
        _Pragma("unroll") for (int r = 0; r < 2; r++) {                      \
            int i = tid + r * 256;                                           \
            bv[r] = *(const uint4*)&B[(long)((k0) + (i >> 4)) * N + n0 +     \
                                      (i & 15) * 8];                         \
        }                                                                    \
    }
#define STORES()                                                             \
    {                                                                        \
        _Pragma("unroll") for (int r = 0; r < 4; r++) {                      \
            int i = tid + r * 256;                                           \
            int m = i >> 3, k4 = (i & 7) * 4;                                \
            *(bf162*)&As[m * APAD + k4] =                                    \
                __floats2bfloat162_rn(av[r].x, av[r].y);                     \
            *(bf162*)&As[m * APAD + k4 + 2] =                                \
                __floats2bfloat162_rn(av[r].z, av[r].w);                     \
        }                                                                    \
        _Pragma("unroll") for (int r = 0; r < 2; r++) {                      \
            int i = tid + r * 256;                                           \
            int k = i >> 4, bb = (i & 15);                                   \
            const bf16* s = (const bf16*)&bv[r];                             \
            _Pragma("unroll") for (int jj = 0; jj < 8; jj++) {               \
                int j = (jj + bb) & 7;                                       \
                Bs[(bb * 8 + j) * BPAD + k] = s[j];                          \
            }                                                                \
        }                                                                    \
    }

    LOADG(0);
    STORES();
    __syncthreads();
    const int nkt = K / BK;
    for (int kt = 0; kt < nkt; kt++) {
        if (kt + 1 < nkt) LOADG((kt + 1) * BK);
#pragma unroll
        for (int kk = 0; kk < 2; kk++) {
            unsigned a[2][4];
#pragma unroll
            for (int mi = 0; mi < 2; mi++) {
                const bf16* p = &As[(wm + mi * 16 + gid) * APAD + kk * 16 + 2 * tq];
                a[mi][0] = *(const unsigned*)p;
                a[mi][1] = *(const unsigned*)(p + 8 * APAD);
                a[mi][2] = *(const unsigned*)(p + 8);
                a[mi][3] = *(const unsigned*)(p + 8 * APAD + 8);
            }
#pragma unroll
            for (int nj = 0; nj < 8; nj++) {
                const bf16* p = &Bs[(wn + nj * 8 + gid) * BPAD + kk * 16 + 2 * tq];
                unsigned b0 = *(const unsigned*)p;
                unsigned b1 = *(const unsigned*)(p + 8);
#pragma unroll
                for (int mi = 0; mi < 2; mi++) mma16(acc[mi][nj], a[mi], b0, b1);
            }
        }
        __syncthreads();
        if (kt + 1 < nkt) {
            STORES();
        }
        __syncthreads();
    }

#pragma unroll
    for (int mi = 0; mi < 2; mi++) {
#pragma unroll
        for (int rr = 0; rr < 2; rr++) {
            int m = m0 + wm + mi * 16 + gid + rr * 8;
            float bi = bias[m];
            if (BF16OUT) {
                bf16* Cm = (bf16*)Cv + (long)bz * strC;
#pragma unroll
                for (int nj = 0; nj < 8; nj++) {
                    int n = n0 + wn + nj * 8 + tq * 2;
                    *(bf162*)&Cm[(long)m * N + n] = __floats2bfloat162_rn(
                        acc[mi][nj][rr * 2] + bi, acc[mi][nj][rr * 2 + 1] + bi);
                }
            } else {
                float* Cm = (float*)Cv + (long)bz * strC;
                const float* rp = resid + (long)bz * strR;
#pragma unroll
                for (int nj = 0; nj < 8; nj++) {
                    int n = n0 + wn + nj * 8 + tq * 2;
                    long off = (long)m * N + n;
                    float2 rv = *(const float2*)&rp[off];
                    float2 r;
                    r.x = acc[mi][nj][rr * 2] + bi + rv.x;
                    r.y = acc[mi][nj][rr * 2 + 1] + bi + rv.y;
                    *(float2*)&Cm[off] = r;
                }
            }
        }
    }
}

// ---------------- Flash attention, bf16 m16n8k16 -----------------------------
#define QP 72
#define KP 72
__global__ void __launch_bounds__(256) attn_bf16() {
    __shared__ bf16 Qs[128 * QP];
    __shared__ bf16 Ks[64 * KP];
    __shared__ bf16 Vs[64 * KP];

    int tid = threadIdx.x, wid = tid >> 5, lane = tid & 31;
    int gid = lane >> 2, tq = lane & 3;
    int t0 = blockIdx.x * 128;
    int bh = blockIdx.y, b = bh >> 4, h = bh & 15;
    const bf16* qp = g_qkv + ((long)b * 3 * NC + (long)h * 64) * NT;
    const bf16* kp = qp + (long)NC * NT;
    const bf16* vp = qp + 2L * (long)NC * NT;
    int wq = wid * 16;

    // stage Q transposed: Qs[q][c]
#pragma unroll
    for (int r = 0; r < 4; r++) {
        int i = tid + r * 256;
        int c = i >> 4, a2 = i & 15;
        uint4 v = *(const uint4*)&qp[(long)c * NT + t0 + a2 * 8];
        const bf16* s = (const bf16*)&v;
#pragma unroll
        for (int jj = 0; jj < 8; jj++) {
            int j = (jj + a2) & 7;
            Qs[(a2 * 8 + j) * QP + c] = s[j];
        }
    }
    __syncthreads();
    unsigned qf[4][4];
#pragma unroll
    for (int kk = 0; kk < 4; kk++) {
        const bf16* p = &Qs[(wq + gid) * QP + kk * 16 + 2 * tq];
        qf[kk][0] = *(const unsigned*)p;
        qf[kk][1] = *(const unsigned*)(p + 8 * QP);
        qf[kk][2] = *(const unsigned*)(p + 8);
        qf[kk][3] = *(const unsigned*)(p + 8 * QP + 8);
    }

    float m_[2] = {-1e30f, -1e30f}, l_[2] = {0.f, 0.f};
    float O[8][4] = {};

    uint4 kvv[2], vvv[2];
#define LOADKV(s0)                                                           \
    {                                                                        \
        _Pragma("unroll") for (int r = 0; r < 2; r++) {                      \
            int i = tid + r * 256;                                           \
            int c = i >> 3, a = i & 7;                                       \
            kvv[r] = *(const uint4*)&kp[(long)c * NT + (s0) + a * 8];        \
            vvv[r] = *(const uint4*)&vp[(long)c * NT + (s0) + a * 8];        \
        }                                                                    \
    }
#define STOREKV()                                                            \
    {                                                                        \
        _Pragma("unroll") for (int r = 0; r < 2; r++) {                      \
            int i = tid + r * 256;                                           \
            int c = i >> 3, a = i & 7;                                       \
            const bf16* s = (const bf16*)&kvv[r];                            \
            _Pragma("unroll") for (int jj = 0; jj < 8; jj++) {               \
                int j = (jj + a) & 7;                                        \
                Ks[(a * 8 + j) * KP + c] = s[j];                             \
            }                                                                \
            *(uint4*)&Vs[c * KP + a * 8] = vvv[r];                           \
        }                                                                    \
    }

    LOADKV(0);
    STOREKV();
    __syncthreads();

    for (int s0 = 0; s0 < NT; s0 += 64) {
        if (s0 + 64 < NT) LOADKV(s0 + 64);

        // S = Q K^T  (m=16 q, n=64 s, k=64 c)
        float S[8][4] = {};
#pragma unroll
        for (int kk = 0; kk < 4; kk++) {
#pragma unroll
            for (int nj = 0; nj < 8; nj++) {
                const bf16* p = &Ks[(nj * 8 + gid) * KP + kk * 16 + 2 * tq];
                mma16(S[nj], qf[kk], *(const unsigned*)p, *(const unsigned*)(p + 8));
            }
        }

        // fragment online softmax (rows gid / gid+8)
#pragma unroll
        for (int nj = 0; nj < 8; nj++)
#pragma unroll
            for (int j = 0; j < 4; j++) S[nj][j] *= 0.125f;
#pragma unroll
        for (int rr = 0; rr < 2; rr++) {
            float mx = -1e30f;
#pragma unroll
            for (int nj = 0; nj < 8; nj++)
                mx = fmaxf(mx, fmaxf(S[nj][rr * 2], S[nj][rr * 2 + 1]));
            mx = fmaxf(mx, __shfl_xor_sync(0xffffffffu, mx, 1));
            mx = fmaxf(mx, __shfl_xor_sync(0xffffffffu, mx, 2));
            float mnew = fmaxf(m_[rr], mx);
            float alpha = __expf(m_[rr] - mnew);
            m_[rr] = mnew;
            float rs = 0.f;
#pragma unroll
            for (int nj = 0; nj < 8; nj++) {
                float p0 = __expf(S[nj][rr * 2] - mnew);
                float p1 = __expf(S[nj][rr * 2 + 1] - mnew);
                S[nj][rr * 2] = p0;
                S[nj][rr * 2 + 1] = p1;
                rs += p0 + p1;
            }
            rs += __shfl_xor_sync(0xffffffffu, rs, 1);
            rs += __shfl_xor_sync(0xffffffffu, rs, 2);
            l_[rr] = l_[rr] * alpha + rs;
#pragma unroll
            for (int nj = 0; nj < 8; nj++) {
                O[nj][rr * 2] *= alpha;
                O[nj][rr * 2 + 1] *= alpha;
            }
        }

        // pack P to bf16 A-fragments (C-layout maps 1:1 onto A-layout)
        unsigned pa[4][4];
#pragma unroll
        for (int kk = 0; kk < 4; kk++) {
            pa[kk][0] = pk(S[2 * kk][0], S[2 * kk][1]);
            pa[kk][1] = pk(S[2 * kk][2], S[2 * kk][3]);
            pa[kk][2] = pk(S[2 * kk + 1][0], S[2 * kk + 1][1]);
            pa[kk][3] = pk(S[2 * kk + 1][2], S[2 * kk + 1][3]);
        }

        // O += P V^T  (m=16 q, n=64 c, k=64 s)
#pragma unroll
        for (int nj = 0; nj < 8; nj++) {
#pragma unroll
            for (int kk = 0; kk < 4; kk++) {
                const bf16* p = &Vs[(nj * 8 + gid) * KP + kk * 16 + 2 * tq];
                mma16(O[nj], pa[kk], *(const unsigned*)p, *(const unsigned*)(p + 8));
            }
        }
        __syncthreads();
        if (s0 + 64 < NT) {
            STOREKV();
        }
        __syncthreads();
    }

    float inv0 = 1.f / l_[0], inv1 = 1.f / l_[1];
    bf16* ap = g_att + ((long)b * NC + (long)h * 64) * NT;
    int q = t0 + wq + gid;
#pragma unroll
    for (int nj = 0; nj < 8; nj++) {
        int c = nj * 8 + 2 * tq;
        ap[(long)c * NT + q] = __float2bfloat16(O[nj][0] * inv0);
        ap[(long)(c + 1) * NT + q] = __float2bfloat16(O[nj][1] * inv0);
        ap[(long)c * NT + q + 8] = __float2bfloat16(O[nj][2] * inv1);
        ap[(long)(c + 1) * NT + q + 8] = __float2bfloat16(O[nj][3] * inv1);
    }
}

// ---------------- launch ------------------------------------------------------
extern "C" void kernel_launch(void* const* d_in, const int* in_sizes, int n_in,
                              void* d_out, int out_size) {
    const float* x = (const float*)d_in[0];
    const float* gn_scale = (const float*)d_in[1];
    const float* gn_bias = (const float*)d_in[2];
    const float* qkv_w = (const float*)d_in[3];
    const float* qkv_b = (const float*)d_in[4];
    const float* proj_w = (const float*)d_in[5];
    const float* proj_b = (const float*)d_in[6];
    float* out = (float*)d_out;

    bf16 *xn_p, *qkv_p, *att_p;
    cudaGetSymbolAddress((void**)&xn_p, g_xn);
    cudaGetSymbolAddress((void**)&qkv_p, g_qkv);
    cudaGetSymbolAddress((void**)&att_p, g_att);

    // 1) GroupNorm -> bf16 xn
    gn_kernel<<<NB * 32, 256>>>(x, gn_scale, gn_bias);

    // 2) QKV GEMM: qkv_w[3C,C] @ xn[b] -> g_qkv (bf16)
    dim3 g1(NT / 128, 3 * NC / 128, NB);
    gemm_bf16<true><<<g1, 256>>>(qkv_w, xn_p, qkv_p, qkv_b, nullptr,
                                 NT, NC, (long)NC * NT, 3L * NC * NT, 0);

    // 3) Attention -> g_att (bf16)
    attn_bf16<<<dim3(NT / 128, NB * NH), 256>>>();

    // 4) proj + bias + residual -> d_out (fp32)
    dim3 g2(NT / 128, NC / 128, NB);
    gemm_bf16<false><<<g2, 256>>>(proj_w, att_p, out, proj_b, x,
                                  NT, NC, (long)NC * NT, (long)NC * NT,
                                  (long)NC * NT);
}